// round 1
// baseline (speedup 1.0000x reference)
#include <cuda_runtime.h>
#include <cuda_bf16.h>
#include <math.h>

// Problem dims
#define NB   64
#define NS   1024
#define NH   512
#define NA   256
#define NF   2048
#define NCAT 4
#define NVOC 1000
#define NEMB 64
#define NCON 4
#define NBS  (NB*NS)          // 65536
#define NFEAT (NCAT*NEMB+NCON) // 260

// ---------------- scratch (device globals; no allocations allowed) -------------
__device__ float g_feat  [(size_t)NBS * NFEAT];
__device__ float g_x     [(size_t)NBS * NH];       // x; reused as z3 after LN1 consumers done
__device__ float g_q     [(size_t)NBS * NA];
__device__ float g_k     [(size_t)NBS * NA];
__device__ float g_v     [(size_t)NBS * NA];
__device__ float g_scores[(size_t)NB * NS * NS];
__device__ float g_zcat  [(size_t)NBS * NH];
__device__ float g_attn  [(size_t)NBS * NH];       // attn out; reused as FFN2 output
__device__ float g_z     [(size_t)NBS * NH];
__device__ float g_h1    [(size_t)NBS * NF];
__device__ float g_pe    [(size_t)NS * NH];

// ---------------- helpers -----------------------------------------------------
__device__ __forceinline__ float warpSum(float v) {
    #pragma unroll
    for (int o = 16; o > 0; o >>= 1) v += __shfl_xor_sync(0xffffffffu, v, o);
    return v;
}
__device__ __forceinline__ float warpMax(float v) {
    #pragma unroll
    for (int o = 16; o > 0; o >>= 1) v = fmaxf(v, __shfl_xor_sync(0xffffffffu, v, o));
    return v;
}

// ---------------- tiled SGEMM -------------------------------------------------
// C[M,N] = alpha * A[M,K] @ op(B) (+bias) (+relu), row-major, strided batch.
// TB=false: B is [K,N] (ldb across K rows). TB=true: B is [N,K] (computes A@B^T).
#define BM 64
#define BN 64
#define BK 16

template<bool TB, bool RELU, bool HASBIAS>
__global__ __launch_bounds__(256)
void sgemm(const float* __restrict__ A, const float* __restrict__ Bm,
           float* __restrict__ C,
           int M, int N, int K, int lda, int ldb, int ldc,
           long long sA, long long sB, long long sC,
           const float* __restrict__ bias, float alpha)
{
    int bz = blockIdx.z;
    A  += (long long)bz * sA;
    Bm += (long long)bz * sB;
    C  += (long long)bz * sC;

    __shared__ float As[BK][BM + 1];
    __shared__ float Bs[BK][BN + 1];

    int tid = threadIdx.x;          // 0..255
    int tx  = tid & 15;             // col group
    int ty  = tid >> 4;             // row group
    int m0  = blockIdx.y * BM;
    int n0  = blockIdx.x * BN;

    float acc[4][4] = {};

    for (int k0 = 0; k0 < K; k0 += BK) {
        // ---- load A tile (64 x 16) ----
        {
            int r = tid >> 4;       // 0..15
            int c = tid & 15;       // 0..15
            #pragma unroll
            for (int i = 0; i < 4; i++) {
                int row = r + 16 * i;
                int gm = m0 + row, gk = k0 + c;
                float vv = 0.f;
                if (gm < M && gk < K) vv = A[(long long)gm * lda + gk];
                As[c][row] = vv;
            }
        }
        // ---- load B tile ----
        if (!TB) {
            #pragma unroll
            for (int i = 0; i < 4; i++) {
                int e  = tid + 256 * i;     // 0..1023
                int kk = e >> 6, n = e & 63;
                int gk = k0 + kk, gn = n0 + n;
                float vv = 0.f;
                if (gk < K && gn < N) vv = Bm[(long long)gk * ldb + gn];
                Bs[kk][n] = vv;
            }
        } else {
            int n = tid >> 2;               // 0..63
            int kbase = (tid & 3) * 4;      // 0,4,8,12
            #pragma unroll
            for (int j = 0; j < 4; j++) {
                int kk = kbase + j;
                int gn = n0 + n, gk = k0 + kk;
                float vv = 0.f;
                if (gn < N && gk < K) vv = Bm[(long long)gn * ldb + gk];
                Bs[kk][n] = vv;
            }
        }
        __syncthreads();

        #pragma unroll
        for (int kk = 0; kk < BK; kk++) {
            float a[4], b[4];
            #pragma unroll
            for (int i = 0; i < 4; i++) a[i] = As[kk][ty * 4 + i];
            #pragma unroll
            for (int j = 0; j < 4; j++) b[j] = Bs[kk][tx * 4 + j];
            #pragma unroll
            for (int i = 0; i < 4; i++)
                #pragma unroll
                for (int j = 0; j < 4; j++)
                    acc[i][j] = fmaf(a[i], b[j], acc[i][j]);
        }
        __syncthreads();
    }

    #pragma unroll
    for (int i = 0; i < 4; i++) {
        int row = m0 + ty * 4 + i;
        if (row >= M) continue;
        #pragma unroll
        for (int j = 0; j < 4; j++) {
            int col = n0 + tx * 4 + j;
            if (col >= N) continue;
            float vv = acc[i][j] * alpha;
            if (HASBIAS) vv += bias[col];
            if (RELU)    vv = fmaxf(vv, 0.f);
            C[(long long)row * ldc + col] = vv;
        }
    }
}

// ---------------- small kernels -----------------------------------------------
__global__ void gather_feat(const int* __restrict__ cate, const float* __restrict__ cont,
                            const float* __restrict__ E, float* __restrict__ feat)
{
    long long t = blockIdx.x * 256LL + threadIdx.x;
    if (t >= (long long)NBS * NFEAT) return;
    int i  = (int)(t / NFEAT);
    int kk = (int)(t % NFEAT);
    float v;
    if (kk < NCAT * NEMB) {
        int f = kk >> 6, e = kk & 63;
        int idx = cate[i * NCAT + f];
        v = E[((long long)f * NVOC + idx) * NEMB + e];
    } else {
        v = cont[i * NCON + (kk - NCAT * NEMB)];
    }
    feat[t] = v;
}

__global__ void compute_pe(float* __restrict__ pe)
{
    int t = blockIdx.x * 256 + threadIdx.x;
    if (t >= NS * NH) return;
    int h = t & (NH - 1);
    int s = t >> 9;
    int i2 = (h >> 1) * 2;
    double freq = exp(-(double)i2 * (9.210340371976184 / (double)NH)); // 10000^{-i/d}
    double ang  = (double)s * freq;
    pe[t] = (float)((h & 1) ? cos(ang) : sin(ang));
}

__global__ void add_pe(float* __restrict__ x, const float* __restrict__ pe)
{
    long long idx = blockIdx.x * 256LL + threadIdx.x;
    if (idx >= (long long)NBS * NH) return;
    x[idx] += pe[idx & ((long long)NS * NH - 1)];
}

// softmax over row of length NS with additive key mask bias; in-place on scores
__global__ void softmax_mask(float* __restrict__ sc, const float* __restrict__ mask)
{
    int row = blockIdx.x;           // b*NS + s
    int b = row >> 10;
    float* p = sc + (long long)row * NS;
    const float* mrow = mask + (long long)b * NS;
    __shared__ float sh[NS];
    __shared__ float red[8];
    int t = threadIdx.x;            // 256

    float lmax = -3.4e38f;
    #pragma unroll
    for (int i = t; i < NS; i += 256) {
        float vv = p[i] + mrow[i] * 1e6f - 1e6f;
        sh[i] = vv;
        lmax = fmaxf(lmax, vv);
    }
    lmax = warpMax(lmax);
    if ((t & 31) == 0) red[t >> 5] = lmax;
    __syncthreads();
    float m;
    {
        float mm = -3.4e38f;
        #pragma unroll
        for (int i = 0; i < 8; i++) mm = fmaxf(mm, red[i]);
        m = mm;
    }
    __syncthreads();

    float ls = 0.f;
    #pragma unroll
    for (int i = t; i < NS; i += 256) {
        float e = expf(sh[i] - m);
        sh[i] = e;
        ls += e;
    }
    ls = warpSum(ls);
    if ((t & 31) == 0) red[t >> 5] = ls;
    __syncthreads();
    float tot = 0.f;
    #pragma unroll
    for (int i = 0; i < 8; i++) tot += red[i];
    float inv = 1.0f / tot;
    #pragma unroll
    for (int i = t; i < NS; i += 256) p[i] = sh[i] * inv;
}

// out = LayerNorm(a + b) * g + be   (row length NH=512, block 256)
__global__ void ln_add(const float* __restrict__ a, const float* __restrict__ bb,
                       const float* __restrict__ g, const float* __restrict__ be,
                       float* __restrict__ out)
{
    int row = blockIdx.x;
    const float* pa = a  + (long long)row * NH;
    const float* pb = bb + (long long)row * NH;
    float* po = out + (long long)row * NH;
    __shared__ float red[8];
    int t = threadIdx.x;

    float v0 = pa[t]       + pb[t];
    float v1 = pa[t + 256] + pb[t + 256];
    float s = warpSum(v0 + v1);
    if ((t & 31) == 0) red[t >> 5] = s;
    __syncthreads();
    float mean;
    {
        float tot = 0.f;
        #pragma unroll
        for (int i = 0; i < 8; i++) tot += red[i];
        mean = tot * (1.0f / NH);
    }
    __syncthreads();

    float d0 = v0 - mean, d1 = v1 - mean;
    float vs = warpSum(d0 * d0 + d1 * d1);
    if ((t & 31) == 0) red[t >> 5] = vs;
    __syncthreads();
    float var = 0.f;
    #pragma unroll
    for (int i = 0; i < 8; i++) var += red[i];
    var *= (1.0f / NH);
    float inv = rsqrtf(var + 1e-5f);

    po[t]       = d0 * inv * g[t]       + be[t];
    po[t + 256] = d1 * inv * g[t + 256] + be[t + 256];
}

__global__ void final_dot(const float* __restrict__ z3, const float* __restrict__ w,
                          const float* __restrict__ b0, float* __restrict__ out)
{
    int row = blockIdx.x;
    const float* pr = z3 + (long long)row * NH;
    int t = threadIdx.x;   // 128
    float s = 0.f;
    #pragma unroll
    for (int i = t; i < NH; i += 128) s = fmaf(pr[i], w[i], s);
    s = warpSum(s);
    __shared__ float red[4];
    if ((t & 31) == 0) red[t >> 5] = s;
    __syncthreads();
    if (t == 0) out[row] = red[0] + red[1] + red[2] + red[3] + b0[0];
}

// ---------------- host side ----------------------------------------------------
static inline void run_gemm(const float* A, const float* B, float* C,
                            int M, int N, int K, int lda, int ldb, int ldc,
                            long long sA, long long sB, long long sC, int batch,
                            const float* bias, float alpha, bool tb, bool relu)
{
    dim3 grid((N + BN - 1) / BN, (M + BM - 1) / BM, batch);
    if (tb) {
        sgemm<true, false, false><<<grid, 256>>>(A, B, C, M, N, K, lda, ldb, ldc, sA, sB, sC, bias, alpha);
    } else if (relu) {
        sgemm<false, true, true><<<grid, 256>>>(A, B, C, M, N, K, lda, ldb, ldc, sA, sB, sC, bias, alpha);
    } else if (bias) {
        sgemm<false, false, true><<<grid, 256>>>(A, B, C, M, N, K, lda, ldb, ldc, sA, sB, sC, bias, alpha);
    } else {
        sgemm<false, false, false><<<grid, 256>>>(A, B, C, M, N, K, lda, ldb, ldc, sA, sB, sC, bias, alpha);
    }
}

extern "C" void kernel_launch(void* const* d_in, const int* in_sizes, int n_in,
                              void* d_out, int out_size)
{
    const int*   cate = (const int*)  d_in[0];
    const float* cont = (const float*)d_in[1];
    const float* mask = (const float*)d_in[2];
    // d_in[3] = targets (unused)
    const float* E    = (const float*)d_in[4];
    const float* Wp   = (const float*)d_in[5];
    const float* WQ[2] = {(const float*)d_in[6], (const float*)d_in[9]};
    const float* WK[2] = {(const float*)d_in[7], (const float*)d_in[10]};
    const float* WV[2] = {(const float*)d_in[8], (const float*)d_in[11]};
    const float* W0   = (const float*)d_in[12];
    const float* ln1g = (const float*)d_in[13];
    const float* ln1b = (const float*)d_in[14];
    const float* Wf1  = (const float*)d_in[15];
    const float* bf1  = (const float*)d_in[16];
    const float* Wf2  = (const float*)d_in[17];
    const float* bf2  = (const float*)d_in[18];
    const float* ln2g = (const float*)d_in[19];
    const float* ln2b = (const float*)d_in[20];
    const float* Wfin = (const float*)d_in[21];
    const float* bfin = (const float*)d_in[22];
    float* out = (float*)d_out;

    float *feat, *x, *q, *k, *v, *scores, *zcat, *attn, *z, *h1, *pe;
    cudaGetSymbolAddress((void**)&feat,   g_feat);
    cudaGetSymbolAddress((void**)&x,      g_x);
    cudaGetSymbolAddress((void**)&q,      g_q);
    cudaGetSymbolAddress((void**)&k,      g_k);
    cudaGetSymbolAddress((void**)&v,      g_v);
    cudaGetSymbolAddress((void**)&scores, g_scores);
    cudaGetSymbolAddress((void**)&zcat,   g_zcat);
    cudaGetSymbolAddress((void**)&attn,   g_attn);
    cudaGetSymbolAddress((void**)&z,      g_z);
    cudaGetSymbolAddress((void**)&h1,     g_h1);
    cudaGetSymbolAddress((void**)&pe,     g_pe);

    // 1) embedding gather + concat
    {
        long long tot = (long long)NBS * NFEAT;
        gather_feat<<<(unsigned)((tot + 255) / 256), 256>>>(cate, cont, E, feat);
    }
    // 2) projection: x = feat @ Wp
    run_gemm(feat, Wp, x, NBS, NH, NFEAT, NFEAT, NH, NH, 0, 0, 0, 1, nullptr, 1.0f, false, false);
    // 3) positional encoding
    compute_pe<<<(NS * NH + 255) / 256, 256>>>(pe);
    add_pe<<<(unsigned)(((long long)NBS * NH + 255) / 256), 256>>>(x, pe);

    // 4) two attention branches (sequential; reuse q/k/v/scores)
    for (int br = 0; br < 2; br++) {
        run_gemm(x, WQ[br], q, NBS, NA, NH, NH, NA, NA, 0, 0, 0, 1, nullptr, 1.0f, false, false);
        run_gemm(x, WK[br], k, NBS, NA, NH, NH, NA, NA, 0, 0, 0, 1, nullptr, 1.0f, false, false);
        run_gemm(x, WV[br], v, NBS, NA, NH, NH, NA, NA, 0, 0, 0, 1, nullptr, 1.0f, false, false);
        // scores[b] = Q[b] @ K[b]^T / 16
        run_gemm(q, k, scores, NS, NS, NA, NA, NA, NS,
                 (long long)NS * NA, (long long)NS * NA, (long long)NS * NS, NB,
                 nullptr, 1.0f / 16.0f, true, false);
        softmax_mask<<<NBS, 256>>>(scores, mask);
        // zcat[b][:, br*NA : br*NA+NA] = P[b] @ V[b]
        run_gemm(scores, v, zcat + br * NA, NS, NA, NS, NS, NA, NH,
                 (long long)NS * NS, (long long)NS * NA, (long long)NS * NH, NB,
                 nullptr, 1.0f, false, false);
    }

    // 5) attn = zcat @ W0
    run_gemm(zcat, W0, attn, NBS, NH, NH, NH, NH, NH, 0, 0, 0, 1, nullptr, 1.0f, false, false);
    // 6) z = LN(x + attn)
    ln_add<<<NBS, 256>>>(x, attn, ln1g, ln1b, z);
    // 7) h1 = relu(z @ Wf1 + bf1)
    run_gemm(z, Wf1, h1, NBS, NF, NH, NH, NF, NF, 0, 0, 0, 1, bf1, 1.0f, false, true);
    // 8) f = h1 @ Wf2 + bf2   (reuse attn buffer)
    run_gemm(h1, Wf2, attn, NBS, NH, NF, NF, NH, NH, 0, 0, 0, 1, bf2, 1.0f, false, false);
    // 9) z3 = LN(z + f)   (reuse x buffer)
    ln_add<<<NBS, 256>>>(z, attn, ln2g, ln2b, x);
    // 10) out = z3 @ Wfin + bfin
    final_dot<<<NBS, 128>>>(x, Wfin, bfin, out);
}

// round 2
// speedup vs baseline: 1.5926x; 1.5926x over previous
#include <cuda_runtime.h>
#include <cuda_bf16.h>
#include <math.h>
#include <stdint.h>

// Problem dims
#define NB   64
#define NS   1024
#define NH   512
#define NA   256
#define NF   2048
#define NCAT 4
#define NVOC 1000
#define NEMB 64
#define NCON 4
#define NBS  (NB*NS)           // 65536
#define NFEAT (NCAT*NEMB+NCON) // 260

// ---------------- scratch (device globals; no allocations allowed) -------------
__device__ float g_feat  [(size_t)NBS * NFEAT];
__device__ float g_x     [(size_t)NBS * NH];
__device__ float g_q     [(size_t)NBS * NA];
__device__ float g_k     [(size_t)NBS * NA];
__device__ float g_v     [(size_t)NBS * NA];
__device__ float g_scores[(size_t)NB * NS * NS];
__device__ float g_zcat  [(size_t)NBS * NH];
__device__ float g_attn  [(size_t)NBS * NH];
__device__ float g_z     [(size_t)NBS * NH];
__device__ float g_h1    [(size_t)NBS * NF];
__device__ float g_pe    [(size_t)NS * NH];

// ---------------- helpers -----------------------------------------------------
__device__ __forceinline__ float warpSum(float v) {
    #pragma unroll
    for (int o = 16; o > 0; o >>= 1) v += __shfl_xor_sync(0xffffffffu, v, o);
    return v;
}
__device__ __forceinline__ float warpMax(float v) {
    #pragma unroll
    for (int o = 16; o > 0; o >>= 1) v = fmaxf(v, __shfl_xor_sync(0xffffffffu, v, o));
    return v;
}

__device__ __forceinline__ void split_tf32(float v, uint32_t& hi, uint32_t& lo) {
    uint32_t h;
    asm("cvt.rna.tf32.f32 %0, %1;" : "=r"(h) : "f"(v));
    float hf = __uint_as_float(h);
    float r  = v - hf;
    uint32_t l;
    asm("cvt.rna.tf32.f32 %0, %1;" : "=r"(l) : "f"(r));
    hi = h; lo = l;
}

__device__ __forceinline__ void mma_tf32(float* c, const uint32_t* a, const uint32_t* b) {
    asm volatile(
        "mma.sync.aligned.m16n8k8.row.col.f32.tf32.tf32.f32 "
        "{%0,%1,%2,%3}, {%4,%5,%6,%7}, {%8,%9}, {%0,%1,%2,%3};"
        : "+f"(c[0]), "+f"(c[1]), "+f"(c[2]), "+f"(c[3])
        : "r"(a[0]), "r"(a[1]), "r"(a[2]), "r"(a[3]), "r"(b[0]), "r"(b[1]));
}

// ---------------- tf32 tensor-core GEMM (3xTF32, near-fp32 accuracy) -----------
// C[M,N] = alpha * A[M,K] @ op(B) (+bias) (+relu) (+pe), row-major, strided batch.
// TB=false: B is [K,N]. TB=true: B is [N,K] (C = A@B^T).
// M, N must be multiples of 128 (true for all call sites). K arbitrary.
#define BM 128
#define BN 128
#define BK 16
#define PAD 8

template<bool TB, bool RELU, bool HASBIAS, bool ADDPE>
__global__ __launch_bounds__(256)
void tgemm(const float* __restrict__ A, const float* __restrict__ Bm,
           float* __restrict__ C,
           int M, int N, int K, int lda, int ldb, int ldc,
           long long sA, long long sB, long long sC,
           const float* __restrict__ bias, const float* __restrict__ pe,
           float alpha)
{
    int bz = blockIdx.z;
    A  += (long long)bz * sA;
    Bm += (long long)bz * sB;
    C  += (long long)bz * sC;

    __shared__ float As[2][BK][BM + PAD];
    __shared__ float Bs[2][BK][BN + PAD];

    const int tid   = threadIdx.x;
    const int lane  = tid & 31;
    const int wid   = tid >> 5;
    const int warpM = wid & 3;       // 4 warps over M (32 rows each)
    const int warpN = wid >> 2;      // 2 warps over N (64 cols each)
    const int gid   = lane >> 2;     // 0..7
    const int tig   = lane & 3;      // 0..3
    const int m0    = blockIdx.y * BM;
    const int n0    = blockIdx.x * BN;

    float acc[2][8][4];
    #pragma unroll
    for (int i = 0; i < 2; i++)
        #pragma unroll
        for (int j = 0; j < 8; j++)
            #pragma unroll
            for (int l = 0; l < 4; l++) acc[i][j][l] = 0.f;

    float4 pa[2], pb[2];

    // ---- loaders ----
    auto ldgA = [&](int k0) {
        #pragma unroll
        for (int i = 0; i < 2; i++) {
            int idx = tid * 2 + i;
            int row = idx >> 2;
            int kq  = (idx & 3) * 4;
            int gk  = k0 + kq;
            const float* p = A + (long long)(m0 + row) * lda + gk;
            if (gk + 3 < K) {
                pa[i] = *(const float4*)p;
            } else {
                pa[i].x = (gk     < K) ? p[0] : 0.f;
                pa[i].y = (gk + 1 < K) ? p[1] : 0.f;
                pa[i].z = (gk + 2 < K) ? p[2] : 0.f;
                pa[i].w = (gk + 3 < K) ? p[3] : 0.f;
            }
        }
    };
    auto stsA = [&](int buf) {
        #pragma unroll
        for (int i = 0; i < 2; i++) {
            int idx = tid * 2 + i;
            int row = idx >> 2;
            int kq  = (idx & 3) * 4;
            As[buf][kq + 0][row] = pa[i].x;
            As[buf][kq + 1][row] = pa[i].y;
            As[buf][kq + 2][row] = pa[i].z;
            As[buf][kq + 3][row] = pa[i].w;
        }
    };
    auto ldgB = [&](int k0) {
        if (!TB) {
            #pragma unroll
            for (int i = 0; i < 2; i++) {
                int idx = tid * 2 + i;
                int k   = idx >> 5;
                int nq  = (idx & 31) * 4;
                if (k0 + k < K) {
                    pb[i] = *(const float4*)(Bm + (long long)(k0 + k) * ldb + n0 + nq);
                } else {
                    pb[i] = make_float4(0.f, 0.f, 0.f, 0.f);
                }
            }
        } else {
            #pragma unroll
            for (int i = 0; i < 2; i++) {
                int idx = tid * 2 + i;
                int n   = idx >> 2;
                int kq  = (idx & 3) * 4;
                int gk  = k0 + kq;
                const float* p = Bm + (long long)(n0 + n) * ldb + gk;
                if (gk + 3 < K) {
                    pb[i] = *(const float4*)p;
                } else {
                    pb[i].x = (gk     < K) ? p[0] : 0.f;
                    pb[i].y = (gk + 1 < K) ? p[1] : 0.f;
                    pb[i].z = (gk + 2 < K) ? p[2] : 0.f;
                    pb[i].w = (gk + 3 < K) ? p[3] : 0.f;
                }
            }
        }
    };
    auto stsB = [&](int buf) {
        if (!TB) {
            #pragma unroll
            for (int i = 0; i < 2; i++) {
                int idx = tid * 2 + i;
                int k   = idx >> 5;
                int nq  = (idx & 31) * 4;
                *(float4*)&Bs[buf][k][nq] = pb[i];
            }
        } else {
            #pragma unroll
            for (int i = 0; i < 2; i++) {
                int idx = tid * 2 + i;
                int n   = idx >> 2;
                int kq  = (idx & 3) * 4;
                Bs[buf][kq + 0][n] = pb[i].x;
                Bs[buf][kq + 1][n] = pb[i].y;
                Bs[buf][kq + 2][n] = pb[i].z;
                Bs[buf][kq + 3][n] = pb[i].w;
            }
        }
    };

    // ---- prologue ----
    ldgA(0); ldgB(0);
    stsA(0); stsB(0);
    __syncthreads();

    int buf = 0;
    for (int k0 = 0; k0 < K; k0 += BK) {
        int nk = k0 + BK;
        bool has = nk < K;
        if (has) { ldgA(nk); ldgB(nk); }

        // ---- compute on current buffer ----
        #pragma unroll
        for (int ks = 0; ks < BK; ks += 8) {
            uint32_t ahi[2][4], alo[2][4], bhi[8][2], blo[8][2];
            #pragma unroll
            for (int mt = 0; mt < 2; mt++) {
                int mb = warpM * 32 + mt * 16;
                float v0 = As[buf][ks + tig    ][mb + gid    ];
                float v1 = As[buf][ks + tig    ][mb + gid + 8];
                float v2 = As[buf][ks + tig + 4][mb + gid    ];
                float v3 = As[buf][ks + tig + 4][mb + gid + 8];
                split_tf32(v0, ahi[mt][0], alo[mt][0]);
                split_tf32(v1, ahi[mt][1], alo[mt][1]);
                split_tf32(v2, ahi[mt][2], alo[mt][2]);
                split_tf32(v3, ahi[mt][3], alo[mt][3]);
            }
            #pragma unroll
            for (int nt = 0; nt < 8; nt++) {
                int nb = warpN * 64 + nt * 8;
                float w0 = Bs[buf][ks + tig    ][nb + gid];
                float w1 = Bs[buf][ks + tig + 4][nb + gid];
                split_tf32(w0, bhi[nt][0], blo[nt][0]);
                split_tf32(w1, bhi[nt][1], blo[nt][1]);
            }
            #pragma unroll
            for (int mt = 0; mt < 2; mt++) {
                #pragma unroll
                for (int nt = 0; nt < 8; nt++) {
                    mma_tf32(acc[mt][nt], ahi[mt], blo[nt]);
                    mma_tf32(acc[mt][nt], alo[mt], bhi[nt]);
                    mma_tf32(acc[mt][nt], ahi[mt], bhi[nt]);
                }
            }
        }

        if (has) {
            stsA(buf ^ 1); stsB(buf ^ 1);
            __syncthreads();
        }
        buf ^= 1;
    }

    // ---- epilogue ----
    #pragma unroll
    for (int mt = 0; mt < 2; mt++) {
        #pragma unroll
        for (int nt = 0; nt < 8; nt++) {
            int r0 = m0 + warpM * 32 + mt * 16 + gid;
            int c0 = n0 + warpN * 64 + nt * 8 + tig * 2;
            #pragma unroll
            for (int h = 0; h < 2; h++) {          // row halves (gid, gid+8)
                int r = r0 + h * 8;
                float* p = C + (long long)r * ldc + c0;
                #pragma unroll
                for (int j = 0; j < 2; j++) {
                    float vv = acc[mt][nt][h * 2 + j] * alpha;
                    int c = c0 + j;
                    if (HASBIAS) vv += bias[c];
                    if (ADDPE)   vv += pe[(long long)(r & (NS - 1)) * NH + c];
                    if (RELU)    vv = fmaxf(vv, 0.f);
                    p[j] = vv;
                }
            }
        }
    }
}

// ---------------- small kernels -----------------------------------------------
__global__ void gather_feat(const int* __restrict__ cate, const float* __restrict__ cont,
                            const float* __restrict__ E, float* __restrict__ feat)
{
    long long t = blockIdx.x * 256LL + threadIdx.x;
    if (t >= (long long)NBS * NFEAT) return;
    int i  = (int)(t / NFEAT);
    int kk = (int)(t % NFEAT);
    float v;
    if (kk < NCAT * NEMB) {
        int f = kk >> 6, e = kk & 63;
        int idx = cate[i * NCAT + f];
        v = E[((long long)f * NVOC + idx) * NEMB + e];
    } else {
        v = cont[i * NCON + (kk - NCAT * NEMB)];
    }
    feat[t] = v;
}

__global__ void compute_pe(float* __restrict__ pe)
{
    int t = blockIdx.x * 256 + threadIdx.x;
    if (t >= NS * NH) return;
    int h = t & (NH - 1);
    int s = t >> 9;
    int i2 = (h >> 1) * 2;
    double freq = exp(-(double)i2 * (9.210340371976184 / (double)NH)); // 10000^{-i/d}
    double ang  = (double)s * freq;
    pe[t] = (float)((h & 1) ? cos(ang) : sin(ang));
}

// softmax over row of length NS with additive key mask bias; in-place on scores
__global__ void softmax_mask(float* __restrict__ sc, const float* __restrict__ mask)
{
    int row = blockIdx.x;           // b*NS + s
    int b = row >> 10;
    float* p = sc + (long long)row * NS;
    const float* mrow = mask + (long long)b * NS;
    __shared__ float sh[NS];
    __shared__ float red[8];
    int t = threadIdx.x;            // 256

    float lmax = -3.4e38f;
    #pragma unroll
    for (int i = t; i < NS; i += 256) {
        float vv = p[i] + mrow[i] * 1e6f - 1e6f;
        sh[i] = vv;
        lmax = fmaxf(lmax, vv);
    }
    lmax = warpMax(lmax);
    if ((t & 31) == 0) red[t >> 5] = lmax;
    __syncthreads();
    float m;
    {
        float mm = -3.4e38f;
        #pragma unroll
        for (int i = 0; i < 8; i++) mm = fmaxf(mm, red[i]);
        m = mm;
    }
    __syncthreads();

    float ls = 0.f;
    #pragma unroll
    for (int i = t; i < NS; i += 256) {
        float e = expf(sh[i] - m);
        sh[i] = e;
        ls += e;
    }
    ls = warpSum(ls);
    if ((t & 31) == 0) red[t >> 5] = ls;
    __syncthreads();
    float tot = 0.f;
    #pragma unroll
    for (int i = 0; i < 8; i++) tot += red[i];
    float inv = 1.0f / tot;
    #pragma unroll
    for (int i = t; i < NS; i += 256) p[i] = sh[i] * inv;
}

// out = LayerNorm(a + b) * g + be   (row length NH=512, block 256)
__global__ void ln_add(const float* __restrict__ a, const float* __restrict__ bb,
                       const float* __restrict__ g, const float* __restrict__ be,
                       float* __restrict__ out)
{
    int row = blockIdx.x;
    const float* pa = a  + (long long)row * NH;
    const float* pb = bb + (long long)row * NH;
    float* po = out + (long long)row * NH;
    __shared__ float red[8];
    int t = threadIdx.x;

    float v0 = pa[t]       + pb[t];
    float v1 = pa[t + 256] + pb[t + 256];
    float s = warpSum(v0 + v1);
    if ((t & 31) == 0) red[t >> 5] = s;
    __syncthreads();
    float mean;
    {
        float tot = 0.f;
        #pragma unroll
        for (int i = 0; i < 8; i++) tot += red[i];
        mean = tot * (1.0f / NH);
    }
    __syncthreads();

    float d0 = v0 - mean, d1 = v1 - mean;
    float vs = warpSum(d0 * d0 + d1 * d1);
    if ((t & 31) == 0) red[t >> 5] = vs;
    __syncthreads();
    float var = 0.f;
    #pragma unroll
    for (int i = 0; i < 8; i++) var += red[i];
    var *= (1.0f / NH);
    float inv = rsqrtf(var + 1e-5f);

    po[t]       = d0 * inv * g[t]       + be[t];
    po[t + 256] = d1 * inv * g[t + 256] + be[t + 256];
}

__global__ void final_dot(const float* __restrict__ z3, const float* __restrict__ w,
                          const float* __restrict__ b0, float* __restrict__ out)
{
    int row = blockIdx.x;
    const float* pr = z3 + (long long)row * NH;
    int t = threadIdx.x;   // 128
    float s = 0.f;
    #pragma unroll
    for (int i = t; i < NH; i += 128) s = fmaf(pr[i], w[i], s);
    s = warpSum(s);
    __shared__ float red[4];
    if ((t & 31) == 0) red[t >> 5] = s;
    __syncthreads();
    if (t == 0) out[row] = red[0] + red[1] + red[2] + red[3] + b0[0];
}

// ---------------- host side ----------------------------------------------------
enum GemmKind { GK_PLAIN, GK_ADDPE, GK_TB, GK_BIAS_RELU, GK_BIAS };

static inline void run_gemm(const float* A, const float* B, float* C,
                            int M, int N, int K, int lda, int ldb, int ldc,
                            long long sA, long long sB, long long sC, int batch,
                            const float* bias, const float* pe, float alpha,
                            GemmKind kind)
{
    dim3 grid(N / BN, M / BM, batch);
    switch (kind) {
    case GK_PLAIN:
        tgemm<false, false, false, false><<<grid, 256>>>(A, B, C, M, N, K, lda, ldb, ldc, sA, sB, sC, bias, pe, alpha);
        break;
    case GK_ADDPE:
        tgemm<false, false, false, true ><<<grid, 256>>>(A, B, C, M, N, K, lda, ldb, ldc, sA, sB, sC, bias, pe, alpha);
        break;
    case GK_TB:
        tgemm<true,  false, false, false><<<grid, 256>>>(A, B, C, M, N, K, lda, ldb, ldc, sA, sB, sC, bias, pe, alpha);
        break;
    case GK_BIAS_RELU:
        tgemm<false, true,  true,  false><<<grid, 256>>>(A, B, C, M, N, K, lda, ldb, ldc, sA, sB, sC, bias, pe, alpha);
        break;
    case GK_BIAS:
        tgemm<false, false, true,  false><<<grid, 256>>>(A, B, C, M, N, K, lda, ldb, ldc, sA, sB, sC, bias, pe, alpha);
        break;
    }
}

extern "C" void kernel_launch(void* const* d_in, const int* in_sizes, int n_in,
                              void* d_out, int out_size)
{
    const int*   cate = (const int*)  d_in[0];
    const float* cont = (const float*)d_in[1];
    const float* mask = (const float*)d_in[2];
    // d_in[3] = targets (unused)
    const float* E    = (const float*)d_in[4];
    const float* Wp   = (const float*)d_in[5];
    const float* WQ[2] = {(const float*)d_in[6], (const float*)d_in[9]};
    const float* WK[2] = {(const float*)d_in[7], (const float*)d_in[10]};
    const float* WV[2] = {(const float*)d_in[8], (const float*)d_in[11]};
    const float* W0   = (const float*)d_in[12];
    const float* ln1g = (const float*)d_in[13];
    const float* ln1b = (const float*)d_in[14];
    const float* Wf1  = (const float*)d_in[15];
    const float* bf1  = (const float*)d_in[16];
    const float* Wf2  = (const float*)d_in[17];
    const float* bf2  = (const float*)d_in[18];
    const float* ln2g = (const float*)d_in[19];
    const float* ln2b = (const float*)d_in[20];
    const float* Wfin = (const float*)d_in[21];
    const float* bfin = (const float*)d_in[22];
    float* out = (float*)d_out;

    float *feat, *x, *q, *k, *v, *scores, *zcat, *attn, *z, *h1, *pe;
    cudaGetSymbolAddress((void**)&feat,   g_feat);
    cudaGetSymbolAddress((void**)&x,      g_x);
    cudaGetSymbolAddress((void**)&q,      g_q);
    cudaGetSymbolAddress((void**)&k,      g_k);
    cudaGetSymbolAddress((void**)&v,      g_v);
    cudaGetSymbolAddress((void**)&scores, g_scores);
    cudaGetSymbolAddress((void**)&zcat,   g_zcat);
    cudaGetSymbolAddress((void**)&attn,   g_attn);
    cudaGetSymbolAddress((void**)&z,      g_z);
    cudaGetSymbolAddress((void**)&h1,     g_h1);
    cudaGetSymbolAddress((void**)&pe,     g_pe);

    // 1) embedding gather + concat
    {
        long long tot = (long long)NBS * NFEAT;
        gather_feat<<<(unsigned)((tot + 255) / 256), 256>>>(cate, cont, E, feat);
    }
    // 2) positional encoding table
    compute_pe<<<(NS * NH + 255) / 256, 256>>>(pe);
    // 3) projection + fused PE add: x = feat @ Wp + pe
    run_gemm(feat, Wp, x, NBS, NH, NFEAT, NFEAT, NH, NH, 0, 0, 0, 1, nullptr, pe, 1.0f, GK_ADDPE);

    // 4) two attention branches (sequential; reuse q/k/v/scores)
    for (int br = 0; br < 2; br++) {
        run_gemm(x, WQ[br], q, NBS, NA, NH, NH, NA, NA, 0, 0, 0, 1, nullptr, nullptr, 1.0f, GK_PLAIN);
        run_gemm(x, WK[br], k, NBS, NA, NH, NH, NA, NA, 0, 0, 0, 1, nullptr, nullptr, 1.0f, GK_PLAIN);
        run_gemm(x, WV[br], v, NBS, NA, NH, NH, NA, NA, 0, 0, 0, 1, nullptr, nullptr, 1.0f, GK_PLAIN);
        // scores[b] = Q[b] @ K[b]^T / 16
        run_gemm(q, k, scores, NS, NS, NA, NA, NA, NS,
                 (long long)NS * NA, (long long)NS * NA, (long long)NS * NS, NB,
                 nullptr, nullptr, 1.0f / 16.0f, GK_TB);
        softmax_mask<<<NBS, 256>>>(scores, mask);
        // zcat[b][:, br*NA : br*NA+NA] = P[b] @ V[b]
        run_gemm(scores, v, zcat + br * NA, NS, NA, NS, NS, NA, NH,
                 (long long)NS * NS, (long long)NS * NA, (long long)NS * NH, NB,
                 nullptr, nullptr, 1.0f, GK_PLAIN);
    }

    // 5) attn = zcat @ W0
    run_gemm(zcat, W0, attn, NBS, NH, NH, NH, NH, NH, 0, 0, 0, 1, nullptr, nullptr, 1.0f, GK_PLAIN);
    // 6) z = LN(x + attn)
    ln_add<<<NBS, 256>>>(x, attn, ln1g, ln1b, z);
    // 7) h1 = relu(z @ Wf1 + bf1)
    run_gemm(z, Wf1, h1, NBS, NF, NH, NH, NF, NF, 0, 0, 0, 1, bf1, nullptr, 1.0f, GK_BIAS_RELU);
    // 8) f = h1 @ Wf2 + bf2   (reuse attn buffer)
    run_gemm(h1, Wf2, attn, NBS, NH, NF, NF, NH, NH, 0, 0, 0, 1, bf2, nullptr, 1.0f, GK_BIAS);
    // 9) z3 = LN(z + f)   (reuse x buffer)
    ln_add<<<NBS, 256>>>(z, attn, ln2g, ln2b, x);
    // 10) out = z3 @ Wfin + bfin
    final_dot<<<NBS, 128>>>(x, Wfin, bfin, out);
}

// round 3
// speedup vs baseline: 2.4770x; 1.5553x over previous
#include <cuda_runtime.h>
#include <cuda_bf16.h>
#include <math.h>
#include <stdint.h>

// Problem dims
#define NB   64
#define NS   1024
#define NH   512
#define NA   256
#define NF   2048
#define NCAT 4
#define NVOC 1000
#define NEMB 64
#define NCON 4
#define NBS  (NB*NS)           // 65536
#define NFEAT (NCAT*NEMB+NCON) // 260

// ---------------- scratch (device globals; no allocations allowed) -------------
__device__ float g_feat  [(size_t)NBS * NFEAT];
__device__ float g_x     [(size_t)NBS * NH];
__device__ float g_q     [(size_t)NBS * NA];
__device__ float g_k     [(size_t)NBS * NA];
__device__ float g_v     [(size_t)NBS * NA];
__device__ float g_scores[(size_t)NB * NS * NS];
__device__ float g_zcat  [(size_t)NBS * NH];
__device__ float g_attn  [(size_t)NBS * NH];
__device__ float g_z     [(size_t)NBS * NH];
__device__ float g_h1    [(size_t)NBS * NF];
__device__ float g_pe    [(size_t)NS * NH];

// ---------------- helpers -----------------------------------------------------
__device__ __forceinline__ float warpSum(float v) {
    #pragma unroll
    for (int o = 16; o > 0; o >>= 1) v += __shfl_xor_sync(0xffffffffu, v, o);
    return v;
}
__device__ __forceinline__ float warpMax(float v) {
    #pragma unroll
    for (int o = 16; o > 0; o >>= 1) v = fmaxf(v, __shfl_xor_sync(0xffffffffu, v, o));
    return v;
}

// split v into bf16 hi + bf16 lo (v ~= hi + lo, to ~2^-17 relative)
__device__ __forceinline__ void split2bf(float v, __nv_bfloat16& h, __nv_bfloat16& l) {
    h = __float2bfloat16_rn(v);
    l = __float2bfloat16_rn(v - __bfloat162float(h));
}
__device__ __forceinline__ uint32_t pack_bf2(__nv_bfloat16 a, __nv_bfloat16 b) {
    // a = k even, b = k odd (low half = first k)
    uint32_t ra = (uint32_t)*(uint16_t*)&a;
    uint32_t rb = (uint32_t)*(uint16_t*)&b;
    return ra | (rb << 16);
}

__device__ __forceinline__ void mma_bf16(float* c, const uint32_t* a, const uint32_t* b) {
    asm volatile(
        "mma.sync.aligned.m16n8k16.row.col.f32.bf16.bf16.f32 "
        "{%0,%1,%2,%3}, {%4,%5,%6,%7}, {%8,%9}, {%0,%1,%2,%3};"
        : "+f"(c[0]), "+f"(c[1]), "+f"(c[2]), "+f"(c[3])
        : "r"(a[0]), "r"(a[1]), "r"(a[2]), "r"(a[3]), "r"(b[0]), "r"(b[1]));
}

// ---------------- bf16x3 tensor-core GEMM (near-fp32 accuracy) -----------------
// C[M,N] = alpha * A[M,K] @ op(B) (+bias) (+relu) (+pe), row-major, strided batch.
// TB=false: B is [K,N]. TB=true: B is [N,K] (C = A@B^T).
// M, N multiples of 128. K arbitrary.
#define BM 128
#define BN 128
#define BK 16
#define LDW (BM + 8)   // words per smem row (BM==BN)

template<bool TB, bool RELU, bool HASBIAS, bool ADDPE>
__global__ __launch_bounds__(256, 2)
void tgemm(const float* __restrict__ A, const float* __restrict__ Bm,
           float* __restrict__ C,
           int M, int N, int K, int lda, int ldb, int ldc,
           long long sA, long long sB, long long sC,
           const float* __restrict__ bias, const float* __restrict__ pe,
           float alpha)
{
    int bz = blockIdx.z;
    A  += (long long)bz * sA;
    Bm += (long long)bz * sB;
    C  += (long long)bz * sC;

    // k-pair packed bf16x2 tiles, hi & lo, double buffered
    __shared__ uint32_t As_hi[2][BK/2][LDW];
    __shared__ uint32_t As_lo[2][BK/2][LDW];
    __shared__ uint32_t Bs_hi[2][BK/2][LDW];
    __shared__ uint32_t Bs_lo[2][BK/2][LDW];

    const int tid   = threadIdx.x;
    const int lane  = tid & 31;
    const int wid   = tid >> 5;
    const int warpM = wid & 3;       // 4 warps over M (32 rows each)
    const int warpN = wid >> 2;      // 2 warps over N (64 cols each)
    const int gid   = lane >> 2;     // 0..7
    const int tig   = lane & 3;      // 0..3
    const int m0    = blockIdx.y * BM;
    const int n0    = blockIdx.x * BN;

    float acc[2][8][4];
    #pragma unroll
    for (int i = 0; i < 2; i++)
        #pragma unroll
        for (int j = 0; j < 8; j++)
            #pragma unroll
            for (int l = 0; l < 4; l++) acc[i][j][l] = 0.f;

    float4 pa[2], pb[2];

    // ---- global loaders (to registers) ----
    auto ldgA = [&](int k0) {
        #pragma unroll
        for (int i = 0; i < 2; i++) {
            int idx = tid * 2 + i;
            int row = idx >> 2;
            int kq  = (idx & 3) * 4;
            int gk  = k0 + kq;
            const float* p = A + (long long)(m0 + row) * lda + gk;
            if (gk + 3 < K) {
                pa[i] = *(const float4*)p;
            } else {
                pa[i].x = (gk     < K) ? p[0] : 0.f;
                pa[i].y = (gk + 1 < K) ? p[1] : 0.f;
                pa[i].z = (gk + 2 < K) ? p[2] : 0.f;
                pa[i].w = (gk + 3 < K) ? p[3] : 0.f;
            }
        }
    };
    auto ldgB = [&](int k0) {
        if (!TB) {
            #pragma unroll
            for (int i = 0; i < 2; i++) {
                int idx = tid * 2 + i;
                int k   = idx >> 5;
                int nq  = (idx & 31) * 4;
                if (k0 + k < K) {
                    pb[i] = *(const float4*)(Bm + (long long)(k0 + k) * ldb + n0 + nq);
                } else {
                    pb[i] = make_float4(0.f, 0.f, 0.f, 0.f);
                }
            }
        } else {
            #pragma unroll
            for (int i = 0; i < 2; i++) {
                int idx = tid * 2 + i;
                int n   = idx >> 2;
                int kq  = (idx & 3) * 4;
                int gk  = k0 + kq;
                const float* p = Bm + (long long)(n0 + n) * ldb + gk;
                if (gk + 3 < K) {
                    pb[i] = *(const float4*)p;
                } else {
                    pb[i].x = (gk     < K) ? p[0] : 0.f;
                    pb[i].y = (gk + 1 < K) ? p[1] : 0.f;
                    pb[i].z = (gk + 2 < K) ? p[2] : 0.f;
                    pb[i].w = (gk + 3 < K) ? p[3] : 0.f;
                }
            }
        }
    };

    // ---- split + store to smem ----
    auto stsA = [&](int buf) {
        #pragma unroll
        for (int i = 0; i < 2; i++) {
            int idx = tid * 2 + i;
            int row = idx >> 2;
            int kp  = (idx & 3) * 2;   // k-pair index: kq/2
            __nv_bfloat16 hx, lx, hy, ly, hz, lz, hw, lw;
            split2bf(pa[i].x, hx, lx); split2bf(pa[i].y, hy, ly);
            split2bf(pa[i].z, hz, lz); split2bf(pa[i].w, hw, lw);
            As_hi[buf][kp    ][row] = pack_bf2(hx, hy);
            As_hi[buf][kp + 1][row] = pack_bf2(hz, hw);
            As_lo[buf][kp    ][row] = pack_bf2(lx, ly);
            As_lo[buf][kp + 1][row] = pack_bf2(lz, lw);
        }
    };
    auto stsB = [&](int buf) {
        if (!TB) {
            #pragma unroll
            for (int i = 0; i < 2; i++) {
                int idx = tid * 2 + i;
                int k   = idx >> 5;
                int nq  = (idx & 31) * 4;
                int kp  = k >> 1;
                int half = k & 1;
                float v[4] = {pb[i].x, pb[i].y, pb[i].z, pb[i].w};
                #pragma unroll
                for (int j = 0; j < 4; j++) {
                    __nv_bfloat16 h, l;
                    split2bf(v[j], h, l);
                    *((uint16_t*)&Bs_hi[buf][kp][nq + j] + half) = *(uint16_t*)&h;
                    *((uint16_t*)&Bs_lo[buf][kp][nq + j] + half) = *(uint16_t*)&l;
                }
            }
        } else {
            #pragma unroll
            for (int i = 0; i < 2; i++) {
                int idx = tid * 2 + i;
                int n   = idx >> 2;
                int kp  = (idx & 3) * 2;
                __nv_bfloat16 hx, lx, hy, ly, hz, lz, hw, lw;
                split2bf(pb[i].x, hx, lx); split2bf(pb[i].y, hy, ly);
                split2bf(pb[i].z, hz, lz); split2bf(pb[i].w, hw, lw);
                Bs_hi[buf][kp    ][n] = pack_bf2(hx, hy);
                Bs_hi[buf][kp + 1][n] = pack_bf2(hz, hw);
                Bs_lo[buf][kp    ][n] = pack_bf2(lx, ly);
                Bs_lo[buf][kp + 1][n] = pack_bf2(lz, lw);
            }
        }
    };

    // ---- prologue ----
    ldgA(0); ldgB(0);
    stsA(0); stsB(0);
    __syncthreads();

    int buf = 0;
    for (int k0 = 0; k0 < K; k0 += BK) {
        int nk = k0 + BK;
        bool has = nk < K;
        if (has) { ldgA(nk); ldgB(nk); }

        // ---- one k16 mma chunk on current buffer ----
        uint32_t ahi[2][4], alo[2][4];
        #pragma unroll
        for (int mt = 0; mt < 2; mt++) {
            int mb = warpM * 32 + mt * 16;
            ahi[mt][0] = As_hi[buf][tig    ][mb + gid];
            ahi[mt][1] = As_hi[buf][tig    ][mb + gid + 8];
            ahi[mt][2] = As_hi[buf][tig + 4][mb + gid];
            ahi[mt][3] = As_hi[buf][tig + 4][mb + gid + 8];
            alo[mt][0] = As_lo[buf][tig    ][mb + gid];
            alo[mt][1] = As_lo[buf][tig    ][mb + gid + 8];
            alo[mt][2] = As_lo[buf][tig + 4][mb + gid];
            alo[mt][3] = As_lo[buf][tig + 4][mb + gid + 8];
        }
        #pragma unroll
        for (int nt = 0; nt < 8; nt++) {
            int nb = warpN * 64 + nt * 8;
            uint32_t bh[2], bl[2];
            bh[0] = Bs_hi[buf][tig    ][nb + gid];
            bh[1] = Bs_hi[buf][tig + 4][nb + gid];
            bl[0] = Bs_lo[buf][tig    ][nb + gid];
            bl[1] = Bs_lo[buf][tig + 4][nb + gid];
            #pragma unroll
            for (int mt = 0; mt < 2; mt++) {
                mma_bf16(acc[mt][nt], ahi[mt], bl);
                mma_bf16(acc[mt][nt], alo[mt], bh);
                mma_bf16(acc[mt][nt], ahi[mt], bh);
            }
        }

        if (has) {
            stsA(buf ^ 1); stsB(buf ^ 1);
            __syncthreads();
        }
        buf ^= 1;
    }

    // ---- epilogue ----
    #pragma unroll
    for (int mt = 0; mt < 2; mt++) {
        #pragma unroll
        for (int nt = 0; nt < 8; nt++) {
            int r0 = m0 + warpM * 32 + mt * 16 + gid;
            int c0 = n0 + warpN * 64 + nt * 8 + tig * 2;
            #pragma unroll
            for (int h = 0; h < 2; h++) {
                int r = r0 + h * 8;
                float* p = C + (long long)r * ldc + c0;
                #pragma unroll
                for (int j = 0; j < 2; j++) {
                    float vv = acc[mt][nt][h * 2 + j] * alpha;
                    int c = c0 + j;
                    if (HASBIAS) vv += bias[c];
                    if (ADDPE)   vv += pe[(long long)(r & (NS - 1)) * NH + c];
                    if (RELU)    vv = fmaxf(vv, 0.f);
                    p[j] = vv;
                }
            }
        }
    }
}

// ---------------- small kernels -----------------------------------------------
__global__ void gather_feat(const int* __restrict__ cate, const float* __restrict__ cont,
                            const float* __restrict__ E, float* __restrict__ feat)
{
    long long t = blockIdx.x * 256LL + threadIdx.x;
    if (t >= (long long)NBS * NFEAT) return;
    int i  = (int)(t / NFEAT);
    int kk = (int)(t % NFEAT);
    float v;
    if (kk < NCAT * NEMB) {
        int f = kk >> 6, e = kk & 63;
        int idx = cate[i * NCAT + f];
        v = E[((long long)f * NVOC + idx) * NEMB + e];
    } else {
        v = cont[i * NCON + (kk - NCAT * NEMB)];
    }
    feat[t] = v;
}

__global__ void compute_pe(float* __restrict__ pe)
{
    int t = blockIdx.x * 256 + threadIdx.x;
    if (t >= NS * NH) return;
    int h = t & (NH - 1);
    int s = t >> 9;
    int i2 = (h >> 1) * 2;
    double freq = exp(-(double)i2 * (9.210340371976184 / (double)NH)); // 10000^{-i/d}
    double ang  = (double)s * freq;
    pe[t] = (float)((h & 1) ? cos(ang) : sin(ang));
}

// softmax over row of length NS with additive key mask bias; in-place on scores
__global__ void softmax_mask(float* __restrict__ sc, const float* __restrict__ mask)
{
    int row = blockIdx.x;           // b*NS + s
    int b = row >> 10;
    float* p = sc + (long long)row * NS;
    const float* mrow = mask + (long long)b * NS;
    __shared__ float sh[NS];
    __shared__ float red[8];
    int t = threadIdx.x;            // 256

    float lmax = -3.4e38f;
    #pragma unroll
    for (int i = t; i < NS; i += 256) {
        // bias computed FIRST (exactly 0 or -1e6) to match reference; no
        // catastrophic quantization of the score against 1e6.
        float bias = mrow[i] * 1e6f - 1e6f;
        float vv = p[i] + bias;
        sh[i] = vv;
        lmax = fmaxf(lmax, vv);
    }
    lmax = warpMax(lmax);
    if ((t & 31) == 0) red[t >> 5] = lmax;
    __syncthreads();
    float m;
    {
        float mm = -3.4e38f;
        #pragma unroll
        for (int i = 0; i < 8; i++) mm = fmaxf(mm, red[i]);
        m = mm;
    }
    __syncthreads();

    float ls = 0.f;
    #pragma unroll
    for (int i = t; i < NS; i += 256) {
        float e = expf(sh[i] - m);
        sh[i] = e;
        ls += e;
    }
    ls = warpSum(ls);
    if ((t & 31) == 0) red[t >> 5] = ls;
    __syncthreads();
    float tot = 0.f;
    #pragma unroll
    for (int i = 0; i < 8; i++) tot += red[i];
    float inv = 1.0f / tot;
    #pragma unroll
    for (int i = t; i < NS; i += 256) p[i] = sh[i] * inv;
}

// out = LayerNorm(a + b) * g + be   (row length NH=512, block 256)
__global__ void ln_add(const float* __restrict__ a, const float* __restrict__ bb,
                       const float* __restrict__ g, const float* __restrict__ be,
                       float* __restrict__ out)
{
    int row = blockIdx.x;
    const float* pa = a  + (long long)row * NH;
    const float* pb = bb + (long long)row * NH;
    float* po = out + (long long)row * NH;
    __shared__ float red[8];
    int t = threadIdx.x;

    float v0 = pa[t]       + pb[t];
    float v1 = pa[t + 256] + pb[t + 256];
    float s = warpSum(v0 + v1);
    if ((t & 31) == 0) red[t >> 5] = s;
    __syncthreads();
    float mean;
    {
        float tot = 0.f;
        #pragma unroll
        for (int i = 0; i < 8; i++) tot += red[i];
        mean = tot * (1.0f / NH);
    }
    __syncthreads();

    float d0 = v0 - mean, d1 = v1 - mean;
    float vs = warpSum(d0 * d0 + d1 * d1);
    if ((t & 31) == 0) red[t >> 5] = vs;
    __syncthreads();
    float var = 0.f;
    #pragma unroll
    for (int i = 0; i < 8; i++) var += red[i];
    var *= (1.0f / NH);
    float inv = rsqrtf(var + 1e-5f);

    po[t]       = d0 * inv * g[t]       + be[t];
    po[t + 256] = d1 * inv * g[t + 256] + be[t + 256];
}

__global__ void final_dot(const float* __restrict__ z3, const float* __restrict__ w,
                          const float* __restrict__ b0, float* __restrict__ out)
{
    int row = blockIdx.x;
    const float* pr = z3 + (long long)row * NH;
    int t = threadIdx.x;   // 128
    float s = 0.f;
    #pragma unroll
    for (int i = t; i < NH; i += 128) s = fmaf(pr[i], w[i], s);
    s = warpSum(s);
    __shared__ float red[4];
    if ((t & 31) == 0) red[t >> 5] = s;
    __syncthreads();
    if (t == 0) out[row] = red[0] + red[1] + red[2] + red[3] + b0[0];
}

// ---------------- host side ----------------------------------------------------
enum GemmKind { GK_PLAIN, GK_ADDPE, GK_TB, GK_BIAS_RELU, GK_BIAS };

static inline void run_gemm(const float* A, const float* B, float* C,
                            int M, int N, int K, int lda, int ldb, int ldc,
                            long long sA, long long sB, long long sC, int batch,
                            const float* bias, const float* pe, float alpha,
                            GemmKind kind)
{
    dim3 grid(N / BN, M / BM, batch);
    switch (kind) {
    case GK_PLAIN:
        tgemm<false, false, false, false><<<grid, 256>>>(A, B, C, M, N, K, lda, ldb, ldc, sA, sB, sC, bias, pe, alpha);
        break;
    case GK_ADDPE:
        tgemm<false, false, false, true ><<<grid, 256>>>(A, B, C, M, N, K, lda, ldb, ldc, sA, sB, sC, bias, pe, alpha);
        break;
    case GK_TB:
        tgemm<true,  false, false, false><<<grid, 256>>>(A, B, C, M, N, K, lda, ldb, ldc, sA, sB, sC, bias, pe, alpha);
        break;
    case GK_BIAS_RELU:
        tgemm<false, true,  true,  false><<<grid, 256>>>(A, B, C, M, N, K, lda, ldb, ldc, sA, sB, sC, bias, pe, alpha);
        break;
    case GK_BIAS:
        tgemm<false, false, true,  false><<<grid, 256>>>(A, B, C, M, N, K, lda, ldb, ldc, sA, sB, sC, bias, pe, alpha);
        break;
    }
}

extern "C" void kernel_launch(void* const* d_in, const int* in_sizes, int n_in,
                              void* d_out, int out_size)
{
    const int*   cate = (const int*)  d_in[0];
    const float* cont = (const float*)d_in[1];
    const float* mask = (const float*)d_in[2];
    // d_in[3] = targets (unused)
    const float* E    = (const float*)d_in[4];
    const float* Wp   = (const float*)d_in[5];
    const float* WQ[2] = {(const float*)d_in[6], (const float*)d_in[9]};
    const float* WK[2] = {(const float*)d_in[7], (const float*)d_in[10]};
    const float* WV[2] = {(const float*)d_in[8], (const float*)d_in[11]};
    const float* W0   = (const float*)d_in[12];
    const float* ln1g = (const float*)d_in[13];
    const float* ln1b = (const float*)d_in[14];
    const float* Wf1  = (const float*)d_in[15];
    const float* bf1  = (const float*)d_in[16];
    const float* Wf2  = (const float*)d_in[17];
    const float* bf2  = (const float*)d_in[18];
    const float* ln2g = (const float*)d_in[19];
    const float* ln2b = (const float*)d_in[20];
    const float* Wfin = (const float*)d_in[21];
    const float* bfin = (const float*)d_in[22];
    float* out = (float*)d_out;

    float *feat, *x, *q, *k, *v, *scores, *zcat, *attn, *z, *h1, *pe;
    cudaGetSymbolAddress((void**)&feat,   g_feat);
    cudaGetSymbolAddress((void**)&x,      g_x);
    cudaGetSymbolAddress((void**)&q,      g_q);
    cudaGetSymbolAddress((void**)&k,      g_k);
    cudaGetSymbolAddress((void**)&v,      g_v);
    cudaGetSymbolAddress((void**)&scores, g_scores);
    cudaGetSymbolAddress((void**)&zcat,   g_zcat);
    cudaGetSymbolAddress((void**)&attn,   g_attn);
    cudaGetSymbolAddress((void**)&z,      g_z);
    cudaGetSymbolAddress((void**)&h1,     g_h1);
    cudaGetSymbolAddress((void**)&pe,     g_pe);

    // 1) embedding gather + concat
    {
        long long tot = (long long)NBS * NFEAT;
        gather_feat<<<(unsigned)((tot + 255) / 256), 256>>>(cate, cont, E, feat);
    }
    // 2) positional encoding table
    compute_pe<<<(NS * NH + 255) / 256, 256>>>(pe);
    // 3) projection + fused PE add: x = feat @ Wp + pe
    run_gemm(feat, Wp, x, NBS, NH, NFEAT, NFEAT, NH, NH, 0, 0, 0, 1, nullptr, pe, 1.0f, GK_ADDPE);

    // 4) two attention branches (sequential; reuse q/k/v/scores)
    for (int br = 0; br < 2; br++) {
        run_gemm(x, WQ[br], q, NBS, NA, NH, NH, NA, NA, 0, 0, 0, 1, nullptr, nullptr, 1.0f, GK_PLAIN);
        run_gemm(x, WK[br], k, NBS, NA, NH, NH, NA, NA, 0, 0, 0, 1, nullptr, nullptr, 1.0f, GK_PLAIN);
        run_gemm(x, WV[br], v, NBS, NA, NH, NH, NA, NA, 0, 0, 0, 1, nullptr, nullptr, 1.0f, GK_PLAIN);
        // scores[b] = Q[b] @ K[b]^T / 16
        run_gemm(q, k, scores, NS, NS, NA, NA, NA, NS,
                 (long long)NS * NA, (long long)NS * NA, (long long)NS * NS, NB,
                 nullptr, nullptr, 1.0f / 16.0f, GK_TB);
        softmax_mask<<<NBS, 256>>>(scores, mask);
        // zcat[b][:, br*NA : br*NA+NA] = P[b] @ V[b]
        run_gemm(scores, v, zcat + br * NA, NS, NA, NS, NS, NA, NH,
                 (long long)NS * NS, (long long)NS * NA, (long long)NS * NH, NB,
                 nullptr, nullptr, 1.0f, GK_PLAIN);
    }

    // 5) attn = zcat @ W0
    run_gemm(zcat, W0, attn, NBS, NH, NH, NH, NH, NH, 0, 0, 0, 1, nullptr, nullptr, 1.0f, GK_PLAIN);
    // 6) z = LN(x + attn)
    ln_add<<<NBS, 256>>>(x, attn, ln1g, ln1b, z);
    // 7) h1 = relu(z @ Wf1 + bf1)
    run_gemm(z, Wf1, h1, NBS, NF, NH, NH, NF, NF, 0, 0, 0, 1, bf1, nullptr, 1.0f, GK_BIAS_RELU);
    // 8) f = h1 @ Wf2 + bf2   (reuse attn buffer)
    run_gemm(h1, Wf2, attn, NBS, NH, NF, NF, NH, NH, 0, 0, 0, 1, bf2, nullptr, 1.0f, GK_BIAS);
    // 9) z3 = LN(z + f)   (reuse x buffer)
    ln_add<<<NBS, 256>>>(z, attn, ln2g, ln2b, x);
    // 10) out = z3 @ Wfin + bfin
    final_dot<<<NBS, 128>>>(x, Wfin, bfin, out);
}